// round 9
// baseline (speedup 1.0000x reference)
#include <cuda_runtime.h>
#include <math.h>

// Problem constants
#define Bc 64
#define Tc 128
#define Dc 1024

#define RPP 16      // rows per pass
#define NPASS 8     // 8 passes x 16 rows = 128 rows (one batch)

// Scratch (device globals: allocation-free per harness rules)
__device__ float g_partial[2 * Bc];
__device__ unsigned int g_done;   // zero at load; reset by last block each run

// ---------------------------------------------------------------------------
// One block per batch (grid 64, 256 threads).
//  Phase 1: stream x[b] (128x1024 f32 = 512 KB) -> xs[b,t] = x[b,t].w_x
//           8 passes x 16 rows; each thread keeps 16 independent LDG.128 in
//           flight (64 KB/SM) -> DRAM latency fully covered at 1 CTA/SM.
//  Phase 2: warp 0 computes this batch's loss from smem:
//           loss_row(j) = log( sum_{t=j+2}^{len-1} exp(xs_t - M) ) + M - xs_{j+2}
//           via warp shfl_down suffix-sum scan (per-batch max shift M).
//           (LSTM head + fc_b cancel along the softmax axis -> dead inputs.)
//  Phase 3: last-done block does the fixed-order 64-way final sum.
// ---------------------------------------------------------------------------
__global__ __launch_bounds__(256) void fused_kernel(const float* __restrict__ x,
                                                    const float* __restrict__ fc_w,
                                                    const int* __restrict__ mask,
                                                    float* __restrict__ out) {
    const int tid  = threadIdx.x;
    const int lane = tid & 31;
    const int warp = tid >> 5;
    const int b    = blockIdx.x;

    __shared__ float s_xs[Tc];
    __shared__ float wsum[8][RPP];

    // Prefetch mask early (latency hidden behind the streaming loop)
    int4 mv = make_int4(0, 0, 0, 0);
    if (warp == 0) mv = ((const int4*)(mask + b * Tc))[lane];

    const float4  w  = ((const float4*)(fc_w + 512))[tid];
    const float4* xb = (const float4*)(x + (size_t)b * Tc * Dc);

    for (int p = 0; p < NPASS; p++) {
        float4 a[RPP];
#pragma unroll
        for (int i = 0; i < RPP; i++)
            a[i] = xb[(p * RPP + i) * 256 + tid];     // 16 independent LDG.128

        float s[RPP];
#pragma unroll
        for (int i = 0; i < RPP; i++)
            s[i] = a[i].x * w.x + a[i].y * w.y + a[i].z * w.z + a[i].w * w.w;

#pragma unroll
        for (int off = 16; off; off >>= 1)
#pragma unroll
            for (int i = 0; i < RPP; i++)
                s[i] += __shfl_xor_sync(0xffffffffu, s[i], off);

        if (lane == 0) {
#pragma unroll
            for (int i = 0; i < RPP; i++) wsum[warp][i] = s[i];
        }
        __syncthreads();
        if (tid < RPP) {
            float t = 0.f;
#pragma unroll
            for (int k = 0; k < 8; k++) t += wsum[k][tid];
            s_xs[p * RPP + tid] = t;
        }
        __syncthreads();   // wsum reused next pass
    }

    // ---- Phase 2: loss for batch b (warp 0 only) ----
    if (warp == 0) {
        int len = mv.x + mv.y + mv.z + mv.w;
#pragma unroll
        for (int off = 16; off; off >>= 1)
            len += __shfl_xor_sync(0xffffffffu, len, off);

        float v[4];
#pragma unroll
        for (int c = 0; c < 4; c++)
            v[c] = s_xs[c * 32 + lane];

        // per-batch max (constant shift; xs is O(1) so no overflow risk)
        float M = fmaxf(fmaxf(v[0], v[1]), fmaxf(v[2], v[3]));
#pragma unroll
        for (int off = 16; off; off >>= 1)
            M = fmaxf(M, __shfl_xor_sync(0xffffffffu, M, off));

        float e[4];
#pragma unroll
        for (int c = 0; c < 4; c++) {
            const int t = c * 32 + lane;
            e[c] = (t < len) ? __expf(v[c] - M) : 0.f;
        }

        // suffix-sum scan, chunk 3 -> 0, carry = sum of later chunks
        float acc = 0.f;
        float carry = 0.f;
#pragma unroll
        for (int c = 3; c >= 0; c--) {
            float ss = e[c];
#pragma unroll
            for (int off = 1; off < 32; off <<= 1) {
                float s2 = __shfl_down_sync(0xffffffffu, ss, off);
                ss += ((lane + off) < 32) ? s2 : 0.f;
            }
            ss += carry;
            const int t = c * 32 + lane;
            if (t >= 2 && t < len)
                acc += __logf(ss) + M - v[c];
            carry = __shfl_sync(0xffffffffu, ss, 0);
        }

        // warp-reduce acc (fixed order -> deterministic)
#pragma unroll
        for (int off = 16; off; off >>= 1)
            acc += __shfl_xor_sync(0xffffffffu, acc, off);

        if (lane == 0) {
            int cnt = len - 2;
            if (cnt < 0) cnt = 0;
            g_partial[2 * b]     = acc;
            g_partial[2 * b + 1] = (float)cnt;
        }
    }

    // ---- Phase 3: last-done block folds the 64 partials ----
    if (tid == 0) {
        __threadfence();
        const unsigned int done = atomicAdd(&g_done, 1u);
        if (done == Bc - 1) {
            __threadfence();
            float tot = 0.f, cnt = 0.f;
#pragma unroll
            for (int k = 0; k < Bc; k++) {
                tot += g_partial[2 * k];
                cnt += g_partial[2 * k + 1];
            }
            out[0] = (cnt > 0.f) ? tot / cnt : 0.f;
            g_done = 0;                  // reset for next graph replay
        }
    }
}

// ---------------------------------------------------------------------------
extern "C" void kernel_launch(void* const* d_in, const int* in_sizes, int n_in,
                              void* d_out, int out_size) {
    const float* x    = (const float*)d_in[0];
    const int*   mask = (const int*)d_in[1];
    // d_in[2..5] (W_ih, W_hh, b_ih, b_hh) and fc_b are dead: the LSTM head
    // contribution is constant along the logsumexp axis and cancels exactly.
    const float* fc_w = (const float*)d_in[6];
    float* out = (float*)d_out;

    fused_kernel<<<Bc, 256>>>(x, fc_w, mask, out);
}

// round 10
// speedup vs baseline: 1.4545x; 1.4545x over previous
#include <cuda_runtime.h>
#include <math.h>

// Problem constants
#define Bc 64
#define Tc 128
#define Dc 1024
#define MU 8192            // B*T rows of xs

#define ROWS_PER_BLK 8

// Scratch (device globals: allocation-free per harness rules)
__device__ float g_xs[MU];
__device__ float g_partial[2 * Bc];
__device__ unsigned int g_done;   // zero at load; reset by last block each run

// ---------------------------------------------------------------------------
// xs[b,t] = x[b,t] . w_x  (w_x = fc_w[512:])
// Grid 1024, block 256; 8 rows/block; 1 weight float4 + 8 independent
// LDG.128 per thread (MLP=8) -> DRAM-latency hidden, ~DRAM-floor bound.
// (R4/R8-proven geometry: regs~16, ~4.5us.)
// ---------------------------------------------------------------------------
__global__ __launch_bounds__(256) void xs_kernel(const float* __restrict__ x,
                                                 const float* __restrict__ fc_w) {
    const int tid = threadIdx.x;
    const int r0  = blockIdx.x * ROWS_PER_BLK;
    const float4* xb = (const float4*)(x + (size_t)r0 * Dc);
    const float4  w  = ((const float4*)(fc_w + 512))[tid];

    float4 a[ROWS_PER_BLK];
#pragma unroll
    for (int i = 0; i < ROWS_PER_BLK; i++)
        a[i] = xb[i * 256 + tid];             // 8 independent LDG.128 in flight

    float s[ROWS_PER_BLK];
#pragma unroll
    for (int i = 0; i < ROWS_PER_BLK; i++)
        s[i] = a[i].x * w.x + a[i].y * w.y + a[i].z * w.z + a[i].w * w.w;

#pragma unroll
    for (int off = 16; off; off >>= 1)
#pragma unroll
        for (int i = 0; i < ROWS_PER_BLK; i++)
            s[i] += __shfl_xor_sync(0xffffffffu, s[i], off);

    __shared__ float wsum[8][ROWS_PER_BLK];
    const int lane = tid & 31, warp = tid >> 5;
    if (lane == 0) {
#pragma unroll
        for (int i = 0; i < ROWS_PER_BLK; i++) wsum[warp][i] = s[i];
    }
    __syncthreads();
    if (tid < ROWS_PER_BLK) {
        float t = 0.f;
#pragma unroll
        for (int k = 0; k < 8; k++) t += wsum[k][tid];
        g_xs[r0 + tid] = t;
    }
}

// ---------------------------------------------------------------------------
// Loss: grid 64, ONE WARP per block, one batch per block -> 64 SMs in
// parallel, each doing a ~300-instruction suffix-scan.
//   loss_row(j) = log( sum_{t=j+2}^{len-1} exp(xs_t - M) ) + M - xs_{j+2}
// with M = per-batch max (constant shift). Suffix sums by warp shfl_down
// suffix scan (pure FADD chain), chunk 3 -> 0 with carry.
// (LSTM head + fc_b cancel along the softmax axis -> dead inputs.)
// Last-done block does the fixed-order 64-way final fold (deterministic).
// ---------------------------------------------------------------------------
__global__ __launch_bounds__(32) void loss_kernel(const int* __restrict__ mask,
                                                  float* __restrict__ out) {
    const int lane = threadIdx.x;
    const int b    = blockIdx.x;

    // len = sum(mask[b,:]) : int4 per lane
    const int4 mv = ((const int4*)(mask + b * Tc))[lane];
    int len = mv.x + mv.y + mv.z + mv.w;
#pragma unroll
    for (int off = 16; off; off >>= 1)
        len += __shfl_xor_sync(0xffffffffu, len, off);

    // xs row: 4 chunks of 32
    float v[4];
#pragma unroll
    for (int c = 0; c < 4; c++)
        v[c] = g_xs[b * Tc + c * 32 + lane];

    // per-batch max (constant shift; xs is O(1) so no overflow risk)
    float M = fmaxf(fmaxf(v[0], v[1]), fmaxf(v[2], v[3]));
#pragma unroll
    for (int off = 16; off; off >>= 1)
        M = fmaxf(M, __shfl_xor_sync(0xffffffffu, M, off));

    // masked exponentials
    float e[4];
#pragma unroll
    for (int c = 0; c < 4; c++) {
        const int t = c * 32 + lane;
        e[c] = (t < len) ? __expf(v[c] - M) : 0.f;
    }

    // suffix-sum scan, chunk 3 -> 0, carry = sum of later chunks
    float acc = 0.f;
    float carry = 0.f;
#pragma unroll
    for (int c = 3; c >= 0; c--) {
        float ss = e[c];
#pragma unroll
        for (int off = 1; off < 32; off <<= 1) {
            float s2 = __shfl_down_sync(0xffffffffu, ss, off);
            ss += ((lane + off) < 32) ? s2 : 0.f;
        }
        ss += carry;
        const int t = c * 32 + lane;
        if (t >= 2 && t < len)
            acc += __logf(ss) + M - v[c];
        carry = __shfl_sync(0xffffffffu, ss, 0);
    }

    // warp-reduce acc (fixed order -> deterministic)
#pragma unroll
    for (int off = 16; off; off >>= 1)
        acc += __shfl_xor_sync(0xffffffffu, acc, off);

    if (lane == 0) {
        int cnt = len - 2;
        if (cnt < 0) cnt = 0;
        g_partial[2 * b]     = acc;
        g_partial[2 * b + 1] = (float)cnt;

        __threadfence();
        const unsigned int done = atomicAdd(&g_done, 1u);
        if (done == Bc - 1) {
            __threadfence();
            float tot = 0.f, cntf = 0.f;
#pragma unroll
            for (int k = 0; k < Bc; k++) {
                tot  += g_partial[2 * k];
                cntf += g_partial[2 * k + 1];
            }
            out[0] = (cntf > 0.f) ? tot / cntf : 0.f;
            g_done = 0;                  // reset for next graph replay
        }
    }
}

// ---------------------------------------------------------------------------
extern "C" void kernel_launch(void* const* d_in, const int* in_sizes, int n_in,
                              void* d_out, int out_size) {
    const float* x    = (const float*)d_in[0];
    const int*   mask = (const int*)d_in[1];
    // d_in[2..5] (W_ih, W_hh, b_ih, b_hh) and fc_b are dead: the LSTM head
    // contribution is constant along the logsumexp axis and cancels exactly.
    const float* fc_w = (const float*)d_in[6];
    float* out = (float*)d_out;

    xs_kernel<<<MU / ROWS_PER_BLK, 256>>>(x, fc_w);
    loss_kernel<<<Bc, 32>>>(mask, out);
}